// round 11
// baseline (speedup 1.0000x reference)
#include <cuda_runtime.h>
#include <cuda_bf16.h>
#include <math.h>
#include <stdint.h>

#define B_ 4
#define N_ 1024
#define M_ 1024
#define D_ 512
#define EPS_ 0.1f
#define INV_EPS 10.0f
#define THRESH_ 0.1f
#define MAX_ITER_ 20
#define MU_CONST 0.0009765725f   /* 1/1024 + 1e-8 */
#define SAS 24                    /* smem row stride (bf16) for 16-wide k-chunk */

// ---------------- device scratch (no allocation allowed) ----------------
__device__ __nv_bfloat16 g_E [(size_t)B_ * N_ * M_];  // exp(-C/eps) bf16
__device__ __nv_bfloat16 g_Et[(size_t)B_ * N_ * M_];  // transposed E bf16
__device__ __nv_bfloat16 g_xh[(size_t)B_ * N_ * D_];
__device__ __nv_bfloat16 g_yh[(size_t)B_ * M_ * D_];
__device__ float g_nx[B_ * N_];
__device__ float g_ny[B_ * M_];
__device__ float g_u [B_ * N_];   // u (for err metric)
__device__ float g_eu[B_ * N_];   // exp(u/eps)
__device__ float g_ev[B_ * M_];   // exp(v/eps)
__device__ float g_err[MAX_ITER_];

__device__ __forceinline__ uint32_t pack_bf2(float a, float b) {
    __nv_bfloat162 t = __floats2bfloat162_rn(a, b);
    return *(uint32_t*)&t;
}
__device__ __forceinline__ float2 b2f(uint32_t u) {
    __nv_bfloat162 h = *reinterpret_cast<__nv_bfloat162*>(&u);
    return __bfloat1622float2(h);
}

// ---------------------------------------------------------------------------
// fused: state init + norms + bf16 prep (xh, yh). 1024 blocks x 8 warps.
// ---------------------------------------------------------------------------
__global__ void k_prep(const float* __restrict__ X, const float* __restrict__ Y,
                       float* out) {
    int tid = threadIdx.x;
    if (blockIdx.x == 0) {
        for (int t = tid; t < B_ * N_; t += 256) { g_u[t] = 0.0f; g_eu[t] = 1.0f; }
        for (int t = tid; t < B_ * M_; t += 256) g_ev[t] = 1.0f;
        if (tid < MAX_ITER_) g_err[tid] = 0.0f;
        if (tid < B_) out[tid] = 0.0f;
    }
    int warp = tid >> 5, lane = tid & 31;
    int r = blockIdx.x * 8 + warp;          // 0..8191
    bool isx = r < B_ * N_;
    int rr = isx ? r : r - B_ * N_;
    const float4* s4 = (const float4*)((isx ? X : Y) + (size_t)rr * D_);
    float ss = 0.0f;
#pragma unroll
    for (int k = 0; k < 4; k++) {
        int idx = k * 32 + lane;
        float4 v = s4[idx];
        ss += v.x * v.x + v.y * v.y + v.z * v.z + v.w * v.w;
        uint2 hi;
        hi.x = pack_bf2(v.x, v.y);
        hi.y = pack_bf2(v.z, v.w);
        size_t e = (size_t)rr * D_ + idx * 4;
        if (isx) *(uint2*)&g_xh[e] = hi;
        else     *(uint2*)&g_yh[e] = hi;
    }
#pragma unroll
    for (int o = 16; o; o >>= 1) ss += __shfl_xor_sync(0xffffffffu, ss, o);
    if (lane == 0) {
        if (isx) g_nx[rr] = sqrtf(ss);
        else     g_ny[rr] = sqrtf(ss);
    }
}

// ---------------------------------------------------------------------------
__device__ __forceinline__ void ldsm4(uint32_t& r0, uint32_t& r1, uint32_t& r2,
                                      uint32_t& r3, uint32_t addr) {
    asm volatile("ldmatrix.sync.aligned.m8n8.x4.shared.b16 {%0,%1,%2,%3},[%4];"
                 : "=r"(r0), "=r"(r1), "=r"(r2), "=r"(r3) : "r"(addr));
}
__device__ __forceinline__ void mma_bf16(float* d, const uint32_t* a,
                                         uint32_t b0, uint32_t b1) {
    asm volatile(
        "mma.sync.aligned.m16n8k16.row.col.f32.bf16.bf16.f32 "
        "{%0,%1,%2,%3},{%4,%5,%6,%7},{%8,%9},{%0,%1,%2,%3};"
        : "+f"(d[0]), "+f"(d[1]), "+f"(d[2]), "+f"(d[3])
        : "r"(a[0]), "r"(a[1]), "r"(a[2]), "r"(a[3]), "r"(b0), "r"(b1));
}

// 128x128 tile, 8 warps (2x4), warp tile 64x32, BK=16, single xh*yh pass.
// Epilogue: cos = dot/max(nx*ny,1e-8); E = exp(10*cos-10) -> g_E, g_Et (bf16).
__global__ __launch_bounds__(256, 2)
void k_gemm() {
    __shared__ __align__(16) char smem_raw[36864];
    __nv_bfloat16* sAB = (__nv_bfloat16*)smem_raw;
    uint32_t sbase = (uint32_t)__cvta_generic_to_shared(smem_raw);

    int b = blockIdx.z;
    int i0 = blockIdx.y * 128;
    int j0 = blockIdx.x * 128;
    int tid = threadIdx.x;
    int lane = tid & 31, warp = tid >> 5;
    int wm = warp >> 2, wn = warp & 3;

    const __nv_bfloat16* Ah = g_xh + (size_t)(b * N_ + i0) * D_;
    const __nv_bfloat16* Bp = g_yh + (size_t)(b * M_ + j0) * D_;

    // loader: 128 rows x 2 chunks of 8 bf16 -> 256 (row,chunk) pairs, 1/thread/matrix
    int lr = tid >> 1;
    int lcH = (tid & 1) * 8;
    int sIdx = lr * SAS + lcH;

    // ldmatrix per-lane offsets (bf16 units)
    int lr8 = lane & 7, seg = lane >> 3;
    int arow = (wm * 64 + lr8 + ((seg & 1) << 3)) * SAS + ((seg >> 1) << 3);
    int brow = (wn * 32 + lr8 + ((seg >> 1) << 3)) * SAS + ((seg & 1) << 3);

    float acc[4][4][4];
#pragma unroll
    for (int mi = 0; mi < 4; mi++)
#pragma unroll
        for (int nj = 0; nj < 4; nj++)
#pragma unroll
            for (int r = 0; r < 4; r++) acc[mi][nj][r] = 0.0f;

    const int STG = 6144;    // stage stride in bf16 ELEMENTS (12288 B)
    const int MATB = 3072;   // per-matrix stride in bf16 elements (6144 B)

    float4 fa, fb;
    fa = *(const float4*)(Ah + lr * D_ + lcH);
    fb = *(const float4*)(Bp + lr * D_ + lcH);
    *(float4*)&sAB[sIdx]        = fa;
    *(float4*)&sAB[MATB + sIdx] = fb;
    __syncthreads();

    for (int s = 0; s < 32; s++) {
        int buf = s & 1;
        if (s + 1 < 32) {
            int k0 = (s + 1) * 16;
            fa = *(const float4*)(Ah + lr * D_ + k0 + lcH);
            fb = *(const float4*)(Bp + lr * D_ + k0 + lcH);
        }
        uint32_t Sb = sbase + buf * (STG * 2);   // byte address of stage
        uint32_t Bb = Sb + MATB * 2;
        uint32_t bfr[2][4];
#pragma unroll
        for (int nt = 0; nt < 2; nt++)
            ldsm4(bfr[nt][0], bfr[nt][1], bfr[nt][2], bfr[nt][3],
                  Bb + (uint32_t)(brow + nt * 16 * SAS) * 2);
        {
            uint32_t a[4][4];
#pragma unroll
            for (int mi = 0; mi < 4; mi++)
                ldsm4(a[mi][0], a[mi][1], a[mi][2], a[mi][3],
                      Sb + (uint32_t)(arow + mi * 16 * SAS) * 2);
#pragma unroll
            for (int mi = 0; mi < 4; mi++)
#pragma unroll
                for (int nj = 0; nj < 4; nj++)
                    mma_bf16(acc[mi][nj], a[mi],
                             bfr[nj >> 1][(nj & 1) * 2], bfr[nj >> 1][(nj & 1) * 2 + 1]);
        }
        if (s + 1 < 32) {
            int e = ((s + 1) & 1) * STG;   // ELEMENT offset
            *(float4*)&sAB[e + sIdx]        = fa;
            *(float4*)&sAB[e + MATB + sIdx] = fb;
        }
        __syncthreads();
    }

    // -------- epilogue: stage dot values half-tile at a time --------
    float* stg = (float*)smem_raw;   // 64 x (stride 132) floats = 33.8 KB (fits)
    const int ST = 132;
    size_t bN = (size_t)b * N_, bM = (size_t)b * M_;
    for (int h = 0; h < 2; h++) {
        __syncthreads();
        if (wm == h) {
#pragma unroll
            for (int mi = 0; mi < 4; mi++)
#pragma unroll
                for (int nj = 0; nj < 4; nj++) {
                    int rr = mi * 16 + (lane >> 2);
                    int cc = wn * 32 + nj * 8 + (lane & 3) * 2;
                    stg[rr * ST + cc]           = acc[mi][nj][0];
                    stg[rr * ST + cc + 1]       = acc[mi][nj][1];
                    stg[(rr + 8) * ST + cc]     = acc[mi][nj][2];
                    stg[(rr + 8) * ST + cc + 1] = acc[mi][nj][3];
                }
        }
        __syncthreads();
        // row-order outputs: E bf16
#pragma unroll
        for (int q = 0; q < 8; q++) {
            int idx = tid + q * 256;
            int r = idx >> 5, cg = (idx & 31) * 4;
            int gi = i0 + h * 64 + r, gj = j0 + cg;
            float nxv = g_nx[bN + gi];
            float4 ny4 = *(const float4*)&g_ny[bM + gj];
            float4 dt = *(const float4*)&stg[r * ST + cg];
            float e0 = __expf(INV_EPS * dt.x / fmaxf(nxv * ny4.x, 1e-8f) - INV_EPS);
            float e1 = __expf(INV_EPS * dt.y / fmaxf(nxv * ny4.y, 1e-8f) - INV_EPS);
            float e2 = __expf(INV_EPS * dt.z / fmaxf(nxv * ny4.z, 1e-8f) - INV_EPS);
            float e3 = __expf(INV_EPS * dt.w / fmaxf(nxv * ny4.w, 1e-8f) - INV_EPS);
            uint2 p;
            p.x = pack_bf2(e0, e1);
            p.y = pack_bf2(e2, e3);
            *(uint2*)&g_E[(bN + gi) * (size_t)M_ + gj] = p;
        }
        // transposed outputs: Et bf16
#pragma unroll
        for (int q = 0; q < 8; q++) {
            int idx = tid + q * 256;
            int jr = idx >> 4, ig = (idx & 15) * 4;
            int gj = j0 + jr;
            int gi0 = i0 + h * 64 + ig;
            float nyv = g_ny[bM + gj];
            float4 nx4 = *(const float4*)&g_nx[bN + gi0];
            float d0 = stg[(ig + 0) * ST + jr];
            float d1 = stg[(ig + 1) * ST + jr];
            float d2 = stg[(ig + 2) * ST + jr];
            float d3 = stg[(ig + 3) * ST + jr];
            float e0 = __expf(INV_EPS * d0 / fmaxf(nx4.x * nyv, 1e-8f) - INV_EPS);
            float e1 = __expf(INV_EPS * d1 / fmaxf(nx4.y * nyv, 1e-8f) - INV_EPS);
            float e2 = __expf(INV_EPS * d2 / fmaxf(nx4.z * nyv, 1e-8f) - INV_EPS);
            float e3 = __expf(INV_EPS * d3 / fmaxf(nx4.w * nyv, 1e-8f) - INV_EPS);
            uint2 p;
            p.x = pack_bf2(e0, e1);
            p.y = pack_bf2(e2, e3);
            *(uint2*)&g_Et[(bM + gj) * (size_t)N_ + gi0] = p;
        }
    }
}

// ---------------------------------------------------------------------------
// sticky freeze flag: any earlier iteration with err < B*thresh
__device__ __forceinline__ int frozen(int it) {
    for (int t = 0; t < it; t++)
        if (g_err[t] < THRESH_ * (float)B_) return 1;
    return 0;
}

// row GEMV: r_i = sum_j E_ij * ev_j ; eu_i = mu / r_i ; accumulate err
__global__ void k_rowE(int iter) {
    __shared__ int sfz;
    __shared__ float serrv;
    __shared__ __align__(16) float sev[M_];
    int tid = threadIdx.x;
    if (tid == 0) { sfz = frozen(iter); serrv = 0.0f; }
    __syncthreads();
    if (sfz) return;
    int b = blockIdx.y;
    {
        float4* d4 = (float4*)sev;
        const float4* s4 = (const float4*)&g_ev[b * M_];
        d4[tid] = s4[tid];
    }
    __syncthreads();

    int warp = tid >> 5, lane = tid & 31;
    const float4* ev4 = (const float4*)sev;
    float dloc = 0.0f;
#pragma unroll
    for (int ri = 0; ri < 2; ri++) {
        int i = blockIdx.x * 16 + ri * 8 + warp;
        const uint4* Er = (const uint4*)(g_E + ((size_t)(b * N_ + i)) * M_);
        float s = 0.0f;
#pragma unroll
        for (int k = 0; k < 4; k++) {
            int c = k * 32 + lane;
            uint4 q = Er[c];
            float4 w0 = ev4[c * 2];
            float4 w1 = ev4[c * 2 + 1];
            float2 a0 = b2f(q.x), a1 = b2f(q.y), a2 = b2f(q.z), a3 = b2f(q.w);
            s += a0.x * w0.x + a0.y * w0.y + a1.x * w0.z + a1.y * w0.w;
            s += a2.x * w1.x + a2.y * w1.y + a3.x * w1.z + a3.y * w1.w;
        }
#pragma unroll
        for (int o = 16; o; o >>= 1) s += __shfl_xor_sync(0xffffffffu, s, o);
        if (lane == 0) {
            int idx = b * N_ + i;
            float eu_new = MU_CONST / s;
            float unew = EPS_ * __logf(eu_new);
            dloc += fabsf(unew - g_u[idx]);
            g_u[idx] = unew;
            g_eu[idx] = eu_new;
        }
    }
    if (lane == 0) atomicAdd(&serrv, dloc);
    __syncthreads();
    if (tid == 0) atomicAdd(&g_err[iter], serrv);
}

// col GEMV: c_j = sum_i Et_ji * eu_i ; ev_j = (nu_j + 1e-8) / c_j
__global__ void k_colE(const float* __restrict__ nu, int iter) {
    __shared__ int sfz;
    __shared__ __align__(16) float seu[N_];
    int tid = threadIdx.x;
    if (tid == 0) sfz = frozen(iter);
    __syncthreads();
    if (sfz) return;
    int b = blockIdx.y;
    {
        float4* d4 = (float4*)seu;
        const float4* s4 = (const float4*)&g_eu[b * N_];
        d4[tid] = s4[tid];
    }
    __syncthreads();

    int warp = tid >> 5, lane = tid & 31;
    const float4* eu4 = (const float4*)seu;
#pragma unroll
    for (int ri = 0; ri < 2; ri++) {
        int j = blockIdx.x * 16 + ri * 8 + warp;
        const uint4* Er = (const uint4*)(g_Et + ((size_t)(b * M_ + j)) * N_);
        float s = 0.0f;
#pragma unroll
        for (int k = 0; k < 4; k++) {
            int c = k * 32 + lane;
            uint4 q = Er[c];
            float4 w0 = eu4[c * 2];
            float4 w1 = eu4[c * 2 + 1];
            float2 a0 = b2f(q.x), a1 = b2f(q.y), a2 = b2f(q.z), a3 = b2f(q.w);
            s += a0.x * w0.x + a0.y * w0.y + a1.x * w0.z + a1.y * w0.w;
            s += a2.x * w1.x + a2.y * w1.y + a3.x * w1.z + a3.y * w1.w;
        }
#pragma unroll
        for (int o = 16; o; o >>= 1) s += __shfl_xor_sync(0xffffffffu, s, o);
        if (lane == 0)
            g_ev[b * M_ + j] = (nu[b * M_ + j] + 1e-8f) / s;
    }
}

// cost[b] = sum_ij eu_i * ev_j * E_ij * C_ij with C = -eps*ln(E)
__global__ void k_cost(float* out) {
    __shared__ __align__(16) float sev[M_];
    int b = blockIdx.y;
    int tid = threadIdx.x;
    {
        float4* d4 = (float4*)sev;
        const float4* s4 = (const float4*)&g_ev[b * M_];
        d4[tid] = s4[tid];
    }
    __syncthreads();

    int warp = tid >> 5, lane = tid & 31;
    const float4* ev4 = (const float4*)sev;
    float tot = 0.0f;
#pragma unroll
    for (int ri = 0; ri < 2; ri++) {
        int i = blockIdx.x * 16 + ri * 8 + warp;
        const uint4* Er = (const uint4*)(g_E + ((size_t)(b * N_ + i)) * M_);
        float s = 0.0f;
#pragma unroll
        for (int k = 0; k < 4; k++) {
            int c = k * 32 + lane;
            uint4 q = Er[c];
            float4 w0 = ev4[c * 2];
            float4 w1 = ev4[c * 2 + 1];
            float2 a0 = b2f(q.x), a1 = b2f(q.y), a2 = b2f(q.z), a3 = b2f(q.w);
            s += a0.x * w0.x * __logf(a0.x) + a0.y * w0.y * __logf(a0.y);
            s += a1.x * w0.z * __logf(a1.x) + a1.y * w0.w * __logf(a1.y);
            s += a2.x * w1.x * __logf(a2.x) + a2.y * w1.y * __logf(a2.y);
            s += a3.x * w1.z * __logf(a3.x) + a3.y * w1.w * __logf(a3.y);
        }
#pragma unroll
        for (int o = 16; o; o >>= 1) s += __shfl_xor_sync(0xffffffffu, s, o);
        if (lane == 0) tot += -EPS_ * g_eu[b * N_ + i] * s;
    }
    if (lane == 0) atomicAdd(&out[b], tot);
}

// ---------------------------------------------------------------------------
extern "C" void kernel_launch(void* const* d_in, const int* in_sizes, int n_in,
                              void* d_out, int out_size) {
    (void)in_sizes; (void)n_in; (void)out_size;
    const float* x  = (const float*)d_in[0];
    const float* y  = (const float*)d_in[1];
    const float* nu = (const float*)d_in[2];
    float* out = (float*)d_out;

    k_prep<<<1024, 256>>>(x, y, out);
    k_gemm<<<dim3(8, 8, B_), 256>>>();
    for (int it = 0; it < MAX_ITER_; ++it) {
        k_rowE<<<dim3(64, B_), 256>>>(it);
        k_colE<<<dim3(64, B_), 256>>>(nu, it);
    }
    k_cost<<<dim3(64, B_), 256>>>(out);
}

// round 13
// speedup vs baseline: 1.8030x; 1.8030x over previous
#include <cuda_runtime.h>
#include <cuda_bf16.h>
#include <math.h>
#include <stdint.h>

#define B_ 4
#define N_ 1024
#define M_ 1024
#define D_ 512
#define EPS_ 0.1f
#define INV_EPS 10.0f
#define THRESH_ 0.1f
#define MAX_ITER_ 20
#define MU_CONST 0.0009765725f   /* 1/1024 + 1e-8 */
#define SAS 24                    /* smem row stride (bf16) for 16-wide k-chunk */
#define NB_LOOP 128               /* persistent loop grid (co-resident: < 148 SMs) */

// ---------------- device scratch (no allocation allowed) ----------------
__device__ __nv_bfloat16 g_E [(size_t)B_ * N_ * M_];  // exp(-C/eps) bf16
__device__ __nv_bfloat16 g_Et[(size_t)B_ * N_ * M_];  // transposed E bf16
__device__ __nv_bfloat16 g_xh[(size_t)B_ * N_ * D_];
__device__ __nv_bfloat16 g_yh[(size_t)B_ * M_ * D_];
__device__ float g_nx[B_ * N_];
__device__ float g_ny[B_ * M_];
__device__ float g_u [B_ * N_];   // u (for err metric)
__device__ float g_eu[B_ * N_];   // exp(u/eps)
__device__ float g_ev[B_ * M_];   // exp(v/eps)
__device__ float g_err[MAX_ITER_];
__device__ unsigned g_cnt;        // grid barrier arrival counter (returns to 0)
__device__ unsigned g_gen;        // grid barrier generation (monotone across replays)

__device__ __forceinline__ uint32_t pack_bf2(float a, float b) {
    __nv_bfloat162 t = __floats2bfloat162_rn(a, b);
    return *(uint32_t*)&t;
}
__device__ __forceinline__ float2 b2f(uint32_t u) {
    __nv_bfloat162 h = *reinterpret_cast<__nv_bfloat162*>(&u);
    return __bfloat1622float2(h);
}

// ---------------------------------------------------------------------------
// fused: state init + norms + bf16 prep (xh, yh). 1024 blocks x 8 warps.
// ---------------------------------------------------------------------------
__global__ void k_prep(const float* __restrict__ X, const float* __restrict__ Y,
                       float* out) {
    int tid = threadIdx.x;
    if (blockIdx.x == 0) {
        for (int t = tid; t < B_ * N_; t += 256) { g_u[t] = 0.0f; g_eu[t] = 1.0f; }
        for (int t = tid; t < B_ * M_; t += 256) g_ev[t] = 1.0f;
        if (tid < MAX_ITER_) g_err[tid] = 0.0f;
        if (tid < B_) out[tid] = 0.0f;
    }
    int warp = tid >> 5, lane = tid & 31;
    int r = blockIdx.x * 8 + warp;          // 0..8191
    bool isx = r < B_ * N_;
    int rr = isx ? r : r - B_ * N_;
    const float4* s4 = (const float4*)((isx ? X : Y) + (size_t)rr * D_);
    float ss = 0.0f;
#pragma unroll
    for (int k = 0; k < 4; k++) {
        int idx = k * 32 + lane;
        float4 v = s4[idx];
        ss += v.x * v.x + v.y * v.y + v.z * v.z + v.w * v.w;
        uint2 hi;
        hi.x = pack_bf2(v.x, v.y);
        hi.y = pack_bf2(v.z, v.w);
        size_t e = (size_t)rr * D_ + idx * 4;
        if (isx) *(uint2*)&g_xh[e] = hi;
        else     *(uint2*)&g_yh[e] = hi;
    }
#pragma unroll
    for (int o = 16; o; o >>= 1) ss += __shfl_xor_sync(0xffffffffu, ss, o);
    if (lane == 0) {
        if (isx) g_nx[rr] = sqrtf(ss);
        else     g_ny[rr] = sqrtf(ss);
    }
}

// ---------------------------------------------------------------------------
__device__ __forceinline__ void ldsm4(uint32_t& r0, uint32_t& r1, uint32_t& r2,
                                      uint32_t& r3, uint32_t addr) {
    asm volatile("ldmatrix.sync.aligned.m8n8.x4.shared.b16 {%0,%1,%2,%3},[%4];"
                 : "=r"(r0), "=r"(r1), "=r"(r2), "=r"(r3) : "r"(addr));
}
__device__ __forceinline__ void mma_bf16(float* d, const uint32_t* a,
                                         uint32_t b0, uint32_t b1) {
    asm volatile(
        "mma.sync.aligned.m16n8k16.row.col.f32.bf16.bf16.f32 "
        "{%0,%1,%2,%3},{%4,%5,%6,%7},{%8,%9},{%0,%1,%2,%3};"
        : "+f"(d[0]), "+f"(d[1]), "+f"(d[2]), "+f"(d[3])
        : "r"(a[0]), "r"(a[1]), "r"(a[2]), "r"(a[3]), "r"(b0), "r"(b1));
}

// 128x128 tile, 8 warps (2x4), warp tile 64x32, BK=16, single xh*yh pass.
// Epilogue: cos = dot/max(nx*ny,1e-8); E = exp(10*cos-10) -> g_E, g_Et (bf16).
__global__ __launch_bounds__(256, 2)
void k_gemm() {
    __shared__ __align__(16) char smem_raw[36864];
    __nv_bfloat16* sAB = (__nv_bfloat16*)smem_raw;
    uint32_t sbase = (uint32_t)__cvta_generic_to_shared(smem_raw);

    int b = blockIdx.z;
    int i0 = blockIdx.y * 128;
    int j0 = blockIdx.x * 128;
    int tid = threadIdx.x;
    int lane = tid & 31, warp = tid >> 5;
    int wm = warp >> 2, wn = warp & 3;

    const __nv_bfloat16* Ah = g_xh + (size_t)(b * N_ + i0) * D_;
    const __nv_bfloat16* Bp = g_yh + (size_t)(b * M_ + j0) * D_;

    int lr = tid >> 1;
    int lcH = (tid & 1) * 8;
    int sIdx = lr * SAS + lcH;

    int lr8 = lane & 7, seg = lane >> 3;
    int arow = (wm * 64 + lr8 + ((seg & 1) << 3)) * SAS + ((seg >> 1) << 3);
    int brow = (wn * 32 + lr8 + ((seg >> 1) << 3)) * SAS + ((seg & 1) << 3);

    float acc[4][4][4];
#pragma unroll
    for (int mi = 0; mi < 4; mi++)
#pragma unroll
        for (int nj = 0; nj < 4; nj++)
#pragma unroll
            for (int r = 0; r < 4; r++) acc[mi][nj][r] = 0.0f;

    const int STG = 6144;    // stage stride in bf16 ELEMENTS
    const int MATB = 3072;   // per-matrix stride in bf16 elements

    float4 fa, fb;
    fa = *(const float4*)(Ah + lr * D_ + lcH);
    fb = *(const float4*)(Bp + lr * D_ + lcH);
    *(float4*)&sAB[sIdx]        = fa;
    *(float4*)&sAB[MATB + sIdx] = fb;
    __syncthreads();

    for (int s = 0; s < 32; s++) {
        int buf = s & 1;
        if (s + 1 < 32) {
            int k0 = (s + 1) * 16;
            fa = *(const float4*)(Ah + lr * D_ + k0 + lcH);
            fb = *(const float4*)(Bp + lr * D_ + k0 + lcH);
        }
        uint32_t Sb = sbase + buf * (STG * 2);
        uint32_t Bb = Sb + MATB * 2;
        uint32_t bfr[2][4];
#pragma unroll
        for (int nt = 0; nt < 2; nt++)
            ldsm4(bfr[nt][0], bfr[nt][1], bfr[nt][2], bfr[nt][3],
                  Bb + (uint32_t)(brow + nt * 16 * SAS) * 2);
        {
            uint32_t a[4][4];
#pragma unroll
            for (int mi = 0; mi < 4; mi++)
                ldsm4(a[mi][0], a[mi][1], a[mi][2], a[mi][3],
                      Sb + (uint32_t)(arow + mi * 16 * SAS) * 2);
#pragma unroll
            for (int mi = 0; mi < 4; mi++)
#pragma unroll
                for (int nj = 0; nj < 4; nj++)
                    mma_bf16(acc[mi][nj], a[mi],
                             bfr[nj >> 1][(nj & 1) * 2], bfr[nj >> 1][(nj & 1) * 2 + 1]);
        }
        if (s + 1 < 32) {
            int e = ((s + 1) & 1) * STG;
            *(float4*)&sAB[e + sIdx]        = fa;
            *(float4*)&sAB[e + MATB + sIdx] = fb;
        }
        __syncthreads();
    }

    // -------- epilogue --------
    float* stg = (float*)smem_raw;
    const int ST = 132;
    size_t bN = (size_t)b * N_, bM = (size_t)b * M_;
    for (int h = 0; h < 2; h++) {
        __syncthreads();
        if (wm == h) {
#pragma unroll
            for (int mi = 0; mi < 4; mi++)
#pragma unroll
                for (int nj = 0; nj < 4; nj++) {
                    int rr = mi * 16 + (lane >> 2);
                    int cc = wn * 32 + nj * 8 + (lane & 3) * 2;
                    stg[rr * ST + cc]           = acc[mi][nj][0];
                    stg[rr * ST + cc + 1]       = acc[mi][nj][1];
                    stg[(rr + 8) * ST + cc]     = acc[mi][nj][2];
                    stg[(rr + 8) * ST + cc + 1] = acc[mi][nj][3];
                }
        }
        __syncthreads();
#pragma unroll
        for (int q = 0; q < 8; q++) {
            int idx = tid + q * 256;
            int r = idx >> 5, cg = (idx & 31) * 4;
            int gi = i0 + h * 64 + r, gj = j0 + cg;
            float nxv = g_nx[bN + gi];
            float4 ny4 = *(const float4*)&g_ny[bM + gj];
            float4 dt = *(const float4*)&stg[r * ST + cg];
            float e0 = __expf(INV_EPS * dt.x / fmaxf(nxv * ny4.x, 1e-8f) - INV_EPS);
            float e1 = __expf(INV_EPS * dt.y / fmaxf(nxv * ny4.y, 1e-8f) - INV_EPS);
            float e2 = __expf(INV_EPS * dt.z / fmaxf(nxv * ny4.z, 1e-8f) - INV_EPS);
            float e3 = __expf(INV_EPS * dt.w / fmaxf(nxv * ny4.w, 1e-8f) - INV_EPS);
            uint2 p;
            p.x = pack_bf2(e0, e1);
            p.y = pack_bf2(e2, e3);
            *(uint2*)&g_E[(bN + gi) * (size_t)M_ + gj] = p;
        }
#pragma unroll
        for (int q = 0; q < 8; q++) {
            int idx = tid + q * 256;
            int jr = idx >> 4, ig = (idx & 15) * 4;
            int gj = j0 + jr;
            int gi0 = i0 + h * 64 + ig;
            float nyv = g_ny[bM + gj];
            float4 nx4 = *(const float4*)&g_nx[bN + gi0];
            float d0 = stg[(ig + 0) * ST + jr];
            float d1 = stg[(ig + 1) * ST + jr];
            float d2 = stg[(ig + 2) * ST + jr];
            float d3 = stg[(ig + 3) * ST + jr];
            float e0 = __expf(INV_EPS * d0 / fmaxf(nx4.x * nyv, 1e-8f) - INV_EPS);
            float e1 = __expf(INV_EPS * d1 / fmaxf(nx4.y * nyv, 1e-8f) - INV_EPS);
            float e2 = __expf(INV_EPS * d2 / fmaxf(nx4.z * nyv, 1e-8f) - INV_EPS);
            float e3 = __expf(INV_EPS * d3 / fmaxf(nx4.w * nyv, 1e-8f) - INV_EPS);
            uint2 p;
            p.x = pack_bf2(e0, e1);
            p.y = pack_bf2(e2, e3);
            *(uint2*)&g_Et[(bM + gj) * (size_t)N_ + gi0] = p;
        }
    }
}

// ---------------------------------------------------------------------------
// persistent Sinkhorn loop + cost. Grid = NB_LOOP blocks (all co-resident).
// Each block: batch b = blk>>5, rows [ (blk&31)*32, +32 ). 4 rows/warp.
// ---------------------------------------------------------------------------
__device__ __forceinline__ void gridbar() {
    __syncthreads();
    if (threadIdx.x == 0) {
        unsigned my = *((volatile unsigned*)&g_gen);
        __threadfence();
        unsigned old = atomicAdd(&g_cnt, 1u);
        if (old == NB_LOOP - 1) {
            atomicExch(&g_cnt, 0u);
            __threadfence();
            atomicAdd(&g_gen, 1u);
        } else {
            while (*((volatile unsigned*)&g_gen) == my) __nanosleep(32);
        }
    }
    __syncthreads();
}

// warp-level GEMV over one bf16 row of length 1024 against smem vec
__device__ __forceinline__ float row_dot(const uint4* __restrict__ Er,
                                         const float4* __restrict__ v4, int lane) {
    float s = 0.0f;
#pragma unroll
    for (int k = 0; k < 4; k++) {
        int c = k * 32 + lane;
        uint4 q = Er[c];
        float4 w0 = v4[c * 2];
        float4 w1 = v4[c * 2 + 1];
        float2 a0 = b2f(q.x), a1 = b2f(q.y), a2 = b2f(q.z), a3 = b2f(q.w);
        s += a0.x * w0.x + a0.y * w0.y + a1.x * w0.z + a1.y * w0.w;
        s += a2.x * w1.x + a2.y * w1.y + a3.x * w1.z + a3.y * w1.w;
    }
#pragma unroll
    for (int o = 16; o; o >>= 1) s += __shfl_xor_sync(0xffffffffu, s, o);
    return s;
}

__global__ __launch_bounds__(256, 2)
void k_loop(const float* __restrict__ nu, float* out) {
    __shared__ __align__(16) float svec[1024];
    __shared__ float serr;
    int tid = threadIdx.x;
    int b = blockIdx.x >> 5;
    int r0 = (blockIdx.x & 31) << 5;
    int warp = tid >> 5, lane = tid & 31;
    const float4* v4 = (const float4*)svec;

    for (int it = 0; it < MAX_ITER_; ++it) {
        // ---- row phase: u update ----
        ((float4*)svec)[tid] = ((const float4*)&g_ev[b * M_])[tid];
        if (tid == 0) serr = 0.0f;
        __syncthreads();
        float dloc = 0.0f;
#pragma unroll
        for (int ri = 0; ri < 4; ri++) {
            int i = r0 + ri * 8 + warp;
            float s = row_dot((const uint4*)(g_E + ((size_t)(b * N_ + i)) * M_), v4, lane);
            if (lane == 0) {
                int idx = b * N_ + i;
                float eu_new = MU_CONST / s;
                float unew = EPS_ * __logf(eu_new);
                dloc += fabsf(unew - g_u[idx]);
                g_u[idx] = unew;
                g_eu[idx] = eu_new;
            }
        }
        if (lane == 0) atomicAdd(&serr, dloc);
        __syncthreads();
        if (tid == 0) atomicAdd(&g_err[it], serr);
        gridbar();

        // ---- col phase: v update ----
        ((float4*)svec)[tid] = ((const float4*)&g_eu[b * N_])[tid];
        __syncthreads();
#pragma unroll
        for (int ri = 0; ri < 4; ri++) {
            int j = r0 + ri * 8 + warp;
            float s = row_dot((const uint4*)(g_Et + ((size_t)(b * M_ + j)) * N_), v4, lane);
            if (lane == 0)
                g_ev[b * M_ + j] = (nu[b * M_ + j] + 1e-8f) / s;
        }
        gridbar();

        // uniform convergence check (reference: freeze from next iter == break)
        if (g_err[it] < THRESH_ * (float)B_) break;
    }

    // ---- cost phase: cost[b] = sum_ij eu_i*ev_j*E_ij*(-eps*ln E_ij) ----
    ((float4*)svec)[tid] = ((const float4*)&g_ev[b * M_])[tid];
    if (tid == 0) serr = 0.0f;
    __syncthreads();
    float tot = 0.0f;
#pragma unroll
    for (int ri = 0; ri < 4; ri++) {
        int i = r0 + ri * 8 + warp;
        const uint4* Er = (const uint4*)(g_E + ((size_t)(b * N_ + i)) * M_);
        float s = 0.0f;
#pragma unroll
        for (int k = 0; k < 4; k++) {
            int c = k * 32 + lane;
            uint4 q = Er[c];
            float4 w0 = v4[c * 2];
            float4 w1 = v4[c * 2 + 1];
            float2 a0 = b2f(q.x), a1 = b2f(q.y), a2 = b2f(q.z), a3 = b2f(q.w);
            s += a0.x * w0.x * __logf(a0.x) + a0.y * w0.y * __logf(a0.y);
            s += a1.x * w0.z * __logf(a1.x) + a1.y * w0.w * __logf(a1.y);
            s += a2.x * w1.x * __logf(a2.x) + a2.y * w1.y * __logf(a2.y);
            s += a3.x * w1.z * __logf(a3.x) + a3.y * w1.w * __logf(a3.y);
        }
#pragma unroll
        for (int o = 16; o; o >>= 1) s += __shfl_xor_sync(0xffffffffu, s, o);
        if (lane == 0) tot += -EPS_ * g_eu[b * N_ + i] * s;
    }
    if (lane == 0) atomicAdd(&serr, tot);
    __syncthreads();
    if (tid == 0) atomicAdd(&out[b], serr);
}

// ---------------------------------------------------------------------------
extern "C" void kernel_launch(void* const* d_in, const int* in_sizes, int n_in,
                              void* d_out, int out_size) {
    (void)in_sizes; (void)n_in; (void)out_size;
    const float* x  = (const float*)d_in[0];
    const float* y  = (const float*)d_in[1];
    const float* nu = (const float*)d_in[2];
    float* out = (float*)d_out;

    k_prep<<<1024, 256>>>(x, y, out);
    k_gemm<<<dim3(8, 8, B_), 256>>>();
    k_loop<<<NB_LOOP, 256>>>(nu, out);
}